// round 17
// baseline (speedup 1.0000x reference)
#include <cuda_runtime.h>

// Problem constants (fixed by the reference setup)
#define NBATCH 32
#define NATOM 256
#define PAIRS_PB 15360
#define NN (NBATCH * PAIRS_PB)      // 491520 total pairs
#define TOTNATOM (NBATCH * NATOM)   // 8192
#define NWAVE 8
#define NSYM 10                     // symmetric channels: 1, x,y,z, xx,xy,xz,yy,yz,zz
#define NORBIT 128
#define CAP 96                      // bin capacity (mean 60, sigma 7.7)
#define APB 8                       // atoms per block (gather role)
#define HSTRIDE 80                  // logical floats per atom slab: 10*8
#define QSTRIDE 84                  // padded quarter-slab stride (bank-clean)
#define NBLK 1024                   // grid size (all-resident by construction)
#define PPB 480                     // pairs per block (32 blocks per batch)

// Per-atom pair bins: record = {ux|sp(2 low bits), uy, uz, d} = 1 float4 (16 B)
__device__ float4 g_rec[(size_t)TOTNATOM * CAP];       // 12.6 MB (L2-resident)
__device__ int    g_cnt[TOTNATOM];                     // zero-init; gather phase resets
// Overflow fallback accumulator [atom][c(10)][w(8)]; gather re-zeroes on use
__device__ float4 g_S[TOTNATOM * (NSYM * NWAVE / 4)];  // 2.6 MB
// Grid barrier (arrive/depart; self-resetting each launch)
__device__ unsigned g_arrive, g_depart;

__device__ __forceinline__ void red_add_v4(float4* ptr, float a, float b, float c, float d) {
    asm volatile("red.global.add.v4.f32 [%0], {%1, %2, %3, %4};"
                 :: "l"(ptr), "f"(a), "f"(b), "f"(c), "f"(d) : "memory");
}
__device__ __forceinline__ float ex2_approx(float x) {
    float r;
    asm("ex2.approx.f32 %0, %1;" : "=f"(r) : "f"(x));
    return r;
}
__device__ __forceinline__ unsigned ld_acquire_u(const unsigned* p) {
    unsigned v;
    asm volatile("ld.acquire.gpu.b32 %0, [%1];" : "=r"(v) : "l"(p) : "memory");
    return v;
}
#define MUL_F32X2(d, a, b) \
    asm("mul.rn.f32x2 %0, %1, %2;" : "=l"(d) : "l"(a), "l"(b))
#define FMA_F32X2(d, a, b, c) \
    asm("fma.rn.f32x2 %0, %1, %2, %3;" : "=l"(d) : "l"(a), "l"(b), "l"(c))
#define PACK2(d, lo, hi) \
    asm("mov.b64 %0, {%1, %2};" : "=l"(d) : "f"(lo), "f"(hi))
#define UNPACK2(lo, hi, s) \
    asm("mov.b64 {%0, %1}, %2;" : "=f"(lo), "=f"(hi) : "l"(s))

// ---------------------------------------------------------------------------
// Fused kernel: every block does (A) 480 pairs of one batch, (B) grid barrier,
// (C) gather+hyper for 8 atoms. Grid 1024 x 128 with __launch_bounds__(128,8)
// guarantees >=8 blocks/SM resident (148*8=1184 >= 1024) -> barrier is safe.
// ---------------------------------------------------------------------------
__global__ void __launch_bounds__(128, 8) fused_kernel(
    const float* __restrict__ cart,        // (totnatom, 3)
    const int*   __restrict__ species,     // (totnatom,)
    const int*   __restrict__ atom_index,  // (2, NN) flattened
    const float* __restrict__ shifts,      // (NN, 3)
    const float* __restrict__ rs,          // (NTYPE, 8)
    const float* __restrict__ inta,        // (NTYPE, 8)
    const float* __restrict__ params,      // (NTYPE, 8)
    const float* __restrict__ hyper,       // (3, 8, 128)
    float* __restrict__ out)               // (totnatom, 128)
{
    __shared__ __align__(16) char sraw[13824];
    const int tid = threadIdx.x;
    const int bid = blockIdx.x;

    // =================== (A) PAIR ROLE: 480 pairs, one batch ===================
    {
        float4* Csm = (float4*)sraw;               // [256] batch cart cache
        int*    Psp = (int*)(sraw + 4096);         // [256] batch species cache
        const int b    = bid >> 5;                 // batch = bid / 32
        const int base = bid * PPB;

        for (int i = tid; i < NATOM; i += 128) {
            const float* cr = cart + (size_t)(b * NATOM + i) * 3;
            Csm[i] = make_float4(__ldg(cr), __ldg(cr + 1), __ldg(cr + 2), 0.f);
            Psp[i] = __ldg(&species[b * NATOM + i]);
        }
        __syncthreads();

        int pp[4], il[4], jl[4], slot[4];
        bool v[4];
#pragma unroll
        for (int k = 0; k < 4; k++) {
            int idx = tid + k * 128;
            v[k]  = idx < PPB;
            pp[k] = base + idx;
            il[k] = v[k] ? __ldg(&atom_index[pp[k]])      : 0;
            jl[k] = v[k] ? __ldg(&atom_index[NN + pp[k]]) : 0;
        }
#pragma unroll
        for (int k = 0; k < 4; k++)
            if (v[k]) slot[k] = atomicAdd(&g_cnt[b * NATOM + il[k]], 1);

        float dx[4], dy[4], dz[4];
        int sp[4];
#pragma unroll
        for (int k = 0; k < 4; k++) {
            float4 ci = Csm[il[k]];
            float4 cj = Csm[jl[k]];
            float sx = v[k] ? __ldg(&shifts[3 * pp[k] + 0]) : 0.f;
            float sy = v[k] ? __ldg(&shifts[3 * pp[k] + 1]) : 0.f;
            float sz = v[k] ? __ldg(&shifts[3 * pp[k] + 2]) : 0.f;
            dx[k] = ci.x - cj.x + sx;
            dy[k] = ci.y - cj.y + sy;
            dz[k] = ci.z - cj.z + sz;
            sp[k] = Psp[jl[k]];
        }

#pragma unroll
        for (int k = 0; k < 4; k++) {
            if (!v[k]) continue;
            float d2  = dx[k] * dx[k] + dy[k] * dy[k] + dz[k] * dz[k];
            float inv = rsqrtf(d2);
            float d   = d2 * inv;
            float ux = dx[k] * inv, uy = dy[k] * inv, uz = dz[k] * inv;
            int ig = b * NATOM + il[k];

            if (slot[k] < CAP) {
                unsigned uxb = (__float_as_uint(ux) & ~3u) | (unsigned)sp[k];
                g_rec[(size_t)ig * CAP + slot[k]] = make_float4(__uint_as_float(uxb), uy, uz, d);
            } else {
                // Overflow fallback (expected never taken): exact red-atomic scatter
                float rc[NWAVE];
#pragma unroll
                for (int w = 0; w < NWAVE; w++) {
                    float tt = d - __ldg(&rs[sp[k] * NWAVE + w]);
                    rc[w] = __expf(__ldg(&inta[sp[k] * NWAVE + w]) * tt * tt)
                          * __ldg(&params[sp[k] * NWAVE + w]);
                }
                float ang[NSYM] = {1.f, ux, uy, uz,
                                   ux * ux, ux * uy, ux * uz, uy * uy, uy * uz, uz * uz};
                float4* Sa = g_S + (size_t)ig * (NSYM * NWAVE / 4);
#pragma unroll
                for (int c = 0; c < NSYM; c++) {
                    float a = ang[c];
                    red_add_v4(&Sa[2 * c + 0], a * rc[0], a * rc[1], a * rc[2], a * rc[3]);
                    red_add_v4(&Sa[2 * c + 1], a * rc[4], a * rc[5], a * rc[6], a * rc[7]);
                }
            }
        }
    }

    // =================== (B) GRID BARRIER (all blocks resident) ===============
    __threadfence();                   // publish g_rec / g_cnt / g_S gpu-wide
    __syncthreads();
    if (tid == 0) {
        atomicAdd(&g_arrive, 1u);
        unsigned ns = 8;
        while (ld_acquire_u(&g_arrive) < NBLK) {
            __nanosleep(ns);
            if (ns < 256) ns += ns;
        }
        unsigned dpt = atomicAdd(&g_depart, 1u) + 1u;
        if (dpt == NBLK) {             // last block resets for the next replay
            atomicExch(&g_depart, 0u);
            atomicExch(&g_arrive, 0u);
        }
    }
    __syncthreads();

    // =================== (C) GATHER ROLE: 8 atoms ============================
    float4* Tbl = (float4*)sraw;                         // [32] {c2,c1,c0,0}
    float*  Ssm = (float*)(sraw + 512);                  // quarters, 10.75 KB
    float2* PkF = (float2*)(sraw + 512 + 10752);         // packed pairs, 2.5 KB

    if (tid < 32) {
        const float L2E = 1.4426950408889634f;
        float R = __ldg(&rs[tid]);
        float A = __ldg(&inta[tid]) * L2E;
        float P = __ldg(&params[tid]);
        Tbl[tid] = make_float4(A, -2.f * A * R, A * R * R + __log2f(P), 0.f);
    }
    __syncthreads();

    const int la = tid >> 4;           // local atom 0..7
    const int q  = (tid >> 2) & 3;     // bin quarter 0..3
    const int wj = tid & 3;            // wave pair index: handles wj and wj+4
    const int a  = bid * APB + la;

    // ---- Phase 1: per-(atom, quarter, wj) dual-wave moment accumulation ----
    const int n  = g_cnt[a];
    const int nc = min(n, CAP);
    if ((tid & 15) == 0) g_cnt[a] = 0; // reset for next replay

    float acc0[NSYM], acc1[NSYM];
    if (n > CAP && q == 0) {           // overflow init + re-zero (expected never)
        float* gs = (float*)(g_S + (size_t)a * (NSYM * NWAVE / 4));
#pragma unroll
        for (int c = 0; c < NSYM; c++) {
            acc0[c] = gs[c * NWAVE + wj];
            acc1[c] = gs[c * NWAVE + wj + 4];
            gs[c * NWAVE + wj]     = 0.f;
            gs[c * NWAVE + wj + 4] = 0.f;
        }
    } else {
#pragma unroll
        for (int c = 0; c < NSYM; c++) { acc0[c] = 0.f; acc1[c] = 0.f; }
    }

    const float4* rec = g_rec + (size_t)a * CAP;
#pragma unroll 2
    for (int p = q; p < nc; p += 4) {
        float4 r = __ldg(&rec[p]);                 // 4-lane broadcast per record
        unsigned uxb = __float_as_uint(r.x);
        int spb = (int)(uxb & 3u) * NWAVE;
        float ux = __uint_as_float(uxb & ~3u);
        float4 cf0 = Tbl[spb + wj];
        float4 cf1 = Tbl[spb + wj + 4];
        float rc0 = ex2_approx(fmaf(fmaf(cf0.x, r.w, cf0.y), r.w, cf0.z));
        float rc1 = ex2_approx(fmaf(fmaf(cf1.x, r.w, cf1.y), r.w, cf1.z));

        acc0[0] += rc0;                            acc1[0] += rc1;
        float tx0 = rc0 * ux,  ty0 = rc0 * r.y,  tz0 = rc0 * r.z;
        float tx1 = rc1 * ux,  ty1 = rc1 * r.y,  tz1 = rc1 * r.z;
        acc0[1] += tx0;        acc1[1] += tx1;
        acc0[2] += ty0;        acc1[2] += ty1;
        acc0[3] += tz0;        acc1[3] += tz1;
        acc0[4] += tx0 * ux;   acc1[4] += tx1 * ux;
        acc0[5] += tx0 * r.y;  acc1[5] += tx1 * r.y;
        acc0[6] += tx0 * r.z;  acc1[6] += tx1 * r.z;
        acc0[7] += ty0 * r.y;  acc1[7] += ty1 * r.y;
        acc0[8] += ty0 * r.z;  acc1[8] += ty1 * r.z;
        acc0[9] += tz0 * r.z;  acc1[9] += tz1 * r.z;
    }

    // ---- Phase 2: stash quarters, combine into packed pair layout ----
#pragma unroll
    for (int c = 0; c < NSYM; c++) {
        Ssm[(la * 4 + q) * QSTRIDE + c * NWAVE + wj]     = acc0[c];
        Ssm[(la * 4 + q) * QSTRIDE + c * NWAVE + wj + 4] = acc1[c];
    }
    __syncthreads();

    {
        // channel weights {1,1,1,1,1,2,2,1,2,1} -> sqrt folded into S
        const float SQ2 = 1.41421356237309515f;
        const float scl[NSYM] = {1.f, 1.f, 1.f, 1.f, 1.f, SQ2, SQ2, 1.f, SQ2, 1.f};
#pragma unroll
        for (int idx = tid; idx < APB * HSTRIDE; idx += 128) {
            int at = idx / HSTRIDE;
            int cw = idx - at * HSTRIDE;
            float v2 = Ssm[(at * 4 + 0) * QSTRIDE + cw] + Ssm[(at * 4 + 1) * QSTRIDE + cw]
                     + Ssm[(at * 4 + 2) * QSTRIDE + cw] + Ssm[(at * 4 + 3) * QSTRIDE + cw];
            ((float*)&PkF[(at >> 1) * (NSYM * NWAVE) + cw])[at & 1] = v2 * scl[cw >> 3];
        }
    }
    __syncthreads();

    // ---- Phase 3: packed f32x2 hyper contraction; thread = orbit column m ----
    const int m = tid;
    unsigned long long hp[3][NWAVE];       // h replicated into both packed halves
#pragma unroll
    for (int k = 0; k < 3; k++)
#pragma unroll
        for (int v2 = 0; v2 < NWAVE; v2++) {
            float hv = __ldg(&hyper[(k * NWAVE + v2) * NORBIT + m]);
            PACK2(hp[k][v2], hv, hv);
        }

    const int k_of[NSYM] = {0, 1, 1, 1, 2, 2, 2, 2, 2, 2};

#pragma unroll 1
    for (int pr = 0; pr < APB / 2; pr++) {
        const ulonglong2* S2 = (const ulonglong2*)(PkF + pr * (NSYM * NWAVE));
        unsigned long long dens;
        PACK2(dens, 0.f, 0.f);
#pragma unroll
        for (int c = 0; c < NSYM; c++) {
            const int k = k_of[c];
            ulonglong2 q0 = S2[c * 4 + 0];   // packed pairs for w=0,1
            ulonglong2 q1 = S2[c * 4 + 1];   // w=2,3
            ulonglong2 q2 = S2[c * 4 + 2];   // w=4,5
            ulonglong2 q3 = S2[c * 4 + 3];   // w=6,7
            unsigned long long tp;
            MUL_F32X2(tp, q0.x, hp[k][0]);
            FMA_F32X2(tp, q0.y, hp[k][1], tp);
            FMA_F32X2(tp, q1.x, hp[k][2], tp);
            FMA_F32X2(tp, q1.y, hp[k][3], tp);
            FMA_F32X2(tp, q2.x, hp[k][4], tp);
            FMA_F32X2(tp, q2.y, hp[k][5], tp);
            FMA_F32X2(tp, q3.x, hp[k][6], tp);
            FMA_F32X2(tp, q3.y, hp[k][7], tp);
            FMA_F32X2(dens, tp, tp, dens);
        }
        float d0, d1;
        UNPACK2(d0, d1, dens);
        const int a0 = bid * APB + 2 * pr;
        out[a0 * NORBIT + m]       = d0;
        out[(a0 + 1) * NORBIT + m] = d1;
    }
}

// ---------------------------------------------------------------------------
// Launch: ONE kernel (counters + barrier self-reset inside)
// ---------------------------------------------------------------------------
extern "C" void kernel_launch(void* const* d_in, const int* in_sizes, int n_in,
                              void* d_out, int out_size) {
    const float* cart       = (const float*)d_in[0];
    // d_in[1] = numatoms (unused by the reference math)
    const int*   species    = (const int*)  d_in[2];
    const int*   atom_index = (const int*)  d_in[3];
    const float* shifts     = (const float*)d_in[4];
    const float* rs         = (const float*)d_in[5];
    const float* inta       = (const float*)d_in[6];
    const float* params     = (const float*)d_in[7];
    const float* hyper      = (const float*)d_in[8];
    float* out = (float*)d_out;

    fused_kernel<<<NBLK, 128>>>(cart, species, atom_index, shifts,
                                rs, inta, params, hyper, out);
}